// round 2
// baseline (speedup 1.0000x reference)
#include <cuda_runtime.h>
#include <cuda_bf16.h>

#define NBINS    65536
#define CAP      4096
#define MAXC     300
#define TOPN     100
#define MAXN     1000448

// ---- scratch (device globals; zero-initialized at module load, and every
//      kernel_launch leaves them zeroed again => deterministic replays) ----
__device__ unsigned short     g_bins[MAXN];
__device__ unsigned int       g_hist[NBINS];
__device__ unsigned int       g_count;
__device__ int                g_thrbin;
__device__ unsigned long long g_cand[CAP];

// ---------------- shared box decode ----------------
__device__ __forceinline__ void decode_core(
    float x1, float y1, float x2, float y2,
    float4 d, float W, float H,
    float& bx1, float& by1, float& bx2, float& by2)
{
    float w  = x2 - x1 + 1.0f;
    float h  = y2 - y1 + 1.0f;
    float cx = x1 + 0.5f*(w - 1.0f);
    float cy = y1 + 0.5f*(h - 1.0f);
    float dx = d.x*0.1f, dy = d.y*0.1f, dw = d.z*0.2f, dh = d.w*0.2f;
    float pcx = dx*w + cx;
    float pcy = dy*h + cy;
    float pw  = expf(dw)*w;
    float ph  = expf(dh)*h;
    bx1 = fminf(fmaxf(pcx - 0.5f*(pw - 1.0f), 0.0f), W);
    by1 = fminf(fmaxf(pcy - 0.5f*(ph - 1.0f), 0.0f), H);
    bx2 = fminf(fmaxf(pcx + 0.5f*(pw - 1.0f), 0.0f), W);
    by2 = fminf(fmaxf(pcy + 0.5f*(ph - 1.0f), 0.0f), H);
}

// ---------------- K1: 4 rois per thread, vectorized ----------------
__global__ void k1_score(const float* __restrict__ cls,
                         const float* __restrict__ bbox,
                         const float* __restrict__ rois,
                         const float* __restrict__ iminfo,
                         int ngrp, int n)
{
    int g = blockIdx.x*blockDim.x + threadIdx.x;
    if (g >= ngrp) return;
    int base = g * 4;
    bool full = (base + 4 <= n);

    float c[20], r[20];
    if (full) {
        const float4* c4 = reinterpret_cast<const float4*>(cls)  + (size_t)g*5;
        const float4* r4 = reinterpret_cast<const float4*>(rois) + (size_t)g*5;
        #pragma unroll
        for (int q = 0; q < 5; q++) {
            float4 t = c4[q];
            c[4*q]=t.x; c[4*q+1]=t.y; c[4*q+2]=t.z; c[4*q+3]=t.w;
        }
        #pragma unroll
        for (int q = 0; q < 5; q++) {
            float4 t = r4[q];
            r[4*q]=t.x; r[4*q+1]=t.y; r[4*q+2]=t.z; r[4*q+3]=t.w;
        }
    } else {
        #pragma unroll
        for (int q = 0; q < 4; q++) {
            if (base + q < n) {
                #pragma unroll
                for (int e = 0; e < 5; e++) {
                    c[q*5+e] = cls [(size_t)(base+q)*5 + e];
                    r[q*5+e] = rois[(size_t)(base+q)*5 + e];
                }
            }
        }
    }

    float W = iminfo[1] - 1.0f, H = iminfo[0] - 1.0f;
    unsigned short outb[4];

    #pragma unroll
    for (int q = 0; q < 4; q++) {
        unsigned short b = 0xFFFFu;
        if (base + q < n) {
            float s0=c[q*5], s1=c[q*5+1], s2=c[q*5+2], s3=c[q*5+3], s4=c[q*5+4];
            float m = s1; int a = 1;
            if (s2 > m) { m = s2; a = 2; }
            if (s3 > m) { m = s3; a = 3; }
            if (s4 > m) { m = s4; a = 4; }
            if ((1.0f - s0 >= 0.2f) && (m > 0.1f)) {
                float4 d = *reinterpret_cast<const float4*>(
                    bbox + (size_t)(base+q)*20 + a*4);
                float bx1, by1, bx2, by2;
                decode_core(r[q*5+1], r[q*5+2], r[q*5+3], r[q*5+4],
                            d, W, H, bx1, by1, bx2, by2);
                float bw = bx2 - bx1 + 1.0f;
                float bh = by2 - by1 + 1.0f;
                if (bw >= 6.0f || bh >= 6.0f) {
                    int bin = (int)(m * 65536.0f);
                    bin = min(max(bin, 0), NBINS - 2);   // 65535 reserved: invalid
                    b = (unsigned short)bin;
                    atomicAdd(&g_hist[bin], 1u);
                }
            }
        }
        outb[q] = b;
    }

    if (full) {
        *reinterpret_cast<ushort4*>(g_bins + base) =
            make_ushort4(outb[0], outb[1], outb[2], outb[3]);
    } else {
        #pragma unroll
        for (int q = 0; q < 4; q++)
            if (base + q < n) g_bins[base + q] = outb[q];
    }
}

// ------- K2: find threshold bin for top-300 (suffix scan), then zero hist ----
__global__ void k2_thresh() {
    __shared__ unsigned int part[1024];
    __shared__ int thr_sh;
    int t = threadIdx.x;
    if (t == 0) thr_sh = 0;

    unsigned int s = 0;
    int cbase = t * (NBINS/1024);            // 64 bins per thread
    #pragma unroll 8
    for (int b = 0; b < NBINS/1024; b++) s += g_hist[cbase + b];
    part[t] = s;
    __syncthreads();

    // Hillis-Steele suffix scan: part[t] = sum_{u>=t} original part[u]
    #pragma unroll
    for (int d = 1; d < 1024; d <<= 1) {
        unsigned int v = part[t] + ((t + d < 1024) ? part[t + d] : 0u);
        __syncthreads();
        part[t] = v;
        __syncthreads();
    }

    // chunk owner: largest t with suffix >= MAXC
    bool owner = (part[t] >= (unsigned)MAXC) &&
                 (t == 1023 || part[t + 1] < (unsigned)MAXC);
    if (owner) {
        unsigned int cum = (t == 1023) ? 0u : part[t + 1];
        for (int b = cbase + (NBINS/1024) - 1; b >= cbase; --b) {
            cum += g_hist[b];
            if (cum >= (unsigned)MAXC) { thr_sh = b; break; }
        }
    }
    __syncthreads();

    // zero histogram for next replay (16B stores)
    uint4* h4 = reinterpret_cast<uint4*>(g_hist);
    #pragma unroll
    for (int j = 0; j < 16; j++) h4[t*16 + j] = make_uint4(0,0,0,0);

    if (t == 0) g_thrbin = thr_sh;
}

// ---------------- K3: collect candidates above threshold ----------------
__global__ void k3_collect(const float* __restrict__ cls, int ngrp8, int n) {
    int g = blockIdx.x*blockDim.x + threadIdx.x;
    if (g >= ngrp8) return;
    uint4 v = reinterpret_cast<const uint4*>(g_bins)[g];
    unsigned int w[4] = {v.x, v.y, v.z, v.w};
    int thr = g_thrbin;
    int base = g * 8;
    #pragma unroll
    for (int l = 0; l < 8; l++) {
        unsigned int b = (w[l >> 1] >> ((l & 1) * 16)) & 0xFFFFu;
        int i = base + l;
        if (b != 0xFFFFu && (int)b >= thr && i < n) {
            const float* c = cls + (size_t)i*5;
            float m = fmaxf(fmaxf(c[1], c[2]), fmaxf(c[3], c[4]));
            unsigned int pos = atomicAdd(&g_count, 1u);
            if (pos < CAP) {
                g_cand[pos] =
                    (((unsigned long long)(~__float_as_uint(m))) << 32) |
                    (unsigned int)i;
            }
        }
    }
}

// ---------------- K4: sort + decode + NMS + output + reset ----------------
__global__ void k4_final(const float* __restrict__ cls,
                         const float* __restrict__ bbox,
                         const float* __restrict__ rois,
                         const float* __restrict__ iminfo,
                         float* __restrict__ out)
{
    __shared__ unsigned long long keys[CAP];   // reused as suppression bitmatrix
    __shared__ float bx[MAXC][4];
    __shared__ float pr[MAXC][5];
    __shared__ float area[MAXC];
    __shared__ int   kept[TOPN];
    __shared__ int   nkept;

    int tid = threadIdx.x;
    int M = (int)min(g_count, (unsigned int)CAP);

    int S = 2; while (S < M) S <<= 1;
    for (int t = tid; t < S; t += blockDim.x)
        keys[t] = (t < M) ? g_cand[t] : 0xFFFFFFFFFFFFFFFFULL;
    __syncthreads();

    // bitonic ascending sort => (score desc, idx asc)
    for (int k = 2; k <= S; k <<= 1) {
        for (int j = k >> 1; j > 0; j >>= 1) {
            for (int t = tid; t < S; t += blockDim.x) {
                int p = t ^ j;
                if (p > t) {
                    unsigned long long a = keys[t];
                    unsigned long long b = keys[p];
                    bool up = ((t & k) == 0);
                    if ((a > b) == up) { keys[t] = b; keys[p] = a; }
                }
            }
            __syncthreads();
        }
    }

    int K = min(M, MAXC);
    float W = iminfo[1] - 1.0f, H = iminfo[0] - 1.0f;

    for (int t = tid; t < K; t += blockDim.x) {
        int i = (int)(unsigned int)(keys[t] & 0xFFFFFFFFULL);
        const float* c = cls + (size_t)i*5;
        float c0=c[0], c1=c[1], c2=c[2], c3=c[3], c4=c[4];
        pr[t][0]=c0; pr[t][1]=c1; pr[t][2]=c2; pr[t][3]=c3; pr[t][4]=c4;
        float m = c1; int a = 1;
        if (c2 > m) { m = c2; a = 2; }
        if (c3 > m) { m = c3; a = 3; }
        if (c4 > m) { m = c4; a = 4; }
        float4 d = *reinterpret_cast<const float4*>(bbox + (size_t)i*20 + a*4);
        float bx1, by1, bx2, by2;
        decode_core(rois[(size_t)i*5+1], rois[(size_t)i*5+2],
                    rois[(size_t)i*5+3], rois[(size_t)i*5+4],
                    d, W, H, bx1, by1, bx2, by2);
        bx[t][0]=bx1; bx[t][1]=by1; bx[t][2]=bx2; bx[t][3]=by2;
        area[t] = (bx2 - bx1) * (by2 - by1);
    }
    __syncthreads();

    // suppression bitmatrix (reuse keys storage)
    unsigned long long* rm = keys;
    const int NW = (MAXC + 63) / 64;  // 5
    for (int task = tid; task < K * NW; task += blockDim.x) {
        int i = task / NW;
        int w = task % NW;
        float ax1=bx[i][0], ay1=bx[i][1], ax2=bx[i][2], ay2=bx[i][3], aa=area[i];
        unsigned long long bits = 0ULL;
        int j0 = w * 64;
        int jend = min(j0 + 64, K);
        for (int j = max(j0, i+1); j < jend; j++) {
            float lx = fmaxf(ax1, bx[j][0]);
            float ly = fmaxf(ay1, bx[j][1]);
            float rx = fminf(ax2, bx[j][2]);
            float ry = fminf(ay2, bx[j][3]);
            float iw = fmaxf(rx - lx, 0.0f);
            float ih = fmaxf(ry - ly, 0.0f);
            float inter = iw * ih;
            float iou = inter / (aa + area[j] - inter);
            if (iou > 0.5f) bits |= 1ULL << (j - j0);
        }
        rm[i*NW + w] = bits;
    }
    __syncthreads();

    // serial greedy walk (exact JAX fori_loop semantics)
    if (tid == 0) {
        unsigned long long sup[NW];
        #pragma unroll
        for (int w = 0; w < NW; w++) sup[w] = 0ULL;
        int cnt = 0;
        for (int i = 0; i < K && cnt < TOPN; i++) {
            if (!((sup[i >> 6] >> (i & 63)) & 1ULL)) {
                kept[cnt++] = i;
                #pragma unroll
                for (int w = 0; w < NW; w++) sup[w] |= rm[i*NW + w];
            }
        }
        nkept = cnt;
    }
    __syncthreads();

    for (int t = tid; t < TOPN*10; t += blockDim.x) out[t] = 0.0f;
    __syncthreads();
    int nk = nkept;
    for (int r = tid; r < nk; r += blockDim.x) {
        int i = kept[r];
        float* o = out + r*10;
        o[0] = 0.0f;
        o[1] = bx[i][0]; o[2] = bx[i][1]; o[3] = bx[i][2]; o[4] = bx[i][3];
        o[5] = pr[i][0]; o[6] = pr[i][1]; o[7] = pr[i][2]; o[8] = pr[i][3]; o[9] = pr[i][4];
    }

    // reset for next graph replay
    if (tid == 0) g_count = 0u;
}

// ---------------- launch ----------------
extern "C" void kernel_launch(void* const* d_in, const int* in_sizes, int n_in,
                              void* d_out, int out_size)
{
    const float* cls    = (const float*)d_in[0];
    const float* bbox   = (const float*)d_in[1];
    const float* rois   = (const float*)d_in[2];
    const float* iminfo = (const float*)d_in[3];
    float* out = (float*)d_out;
    int n = in_sizes[0] / 5;
    if (n > MAXN) n = MAXN;

    int ngrp4 = (n + 3) / 4;
    int ngrp8 = (n + 7) / 8;

    k1_score <<<(ngrp4 + 255)/256, 256>>>(cls, bbox, rois, iminfo, ngrp4, n);
    k2_thresh<<<1, 1024>>>();
    k3_collect<<<(ngrp8 + 255)/256, 256>>>(cls, ngrp8, n);
    k4_final <<<1, 1024>>>(cls, bbox, rois, iminfo, out);
}

// round 3
// speedup vs baseline: 1.0661x; 1.0661x over previous
#include <cuda_runtime.h>
#include <cuda_bf16.h>

#define NBINS    65536
#define CAP      4096
#define MAXC     300
#define TOPN     100
#define MAXN     1000448

// ---- scratch (device globals; zero-init at load; every launch re-zeroes) ----
__device__ unsigned short     g_bins[MAXN];
__device__ unsigned int       g_hist[NBINS];
__device__ unsigned int       g_count;
__device__ int                g_thrbin;
__device__ unsigned long long g_cand[CAP];

// ---------------- shared box decode ----------------
__device__ __forceinline__ void decode_core(
    float x1, float y1, float x2, float y2,
    float4 d, float W, float H,
    float& bx1, float& by1, float& bx2, float& by2)
{
    float w  = x2 - x1 + 1.0f;
    float h  = y2 - y1 + 1.0f;
    float cx = x1 + 0.5f*(w - 1.0f);
    float cy = y1 + 0.5f*(h - 1.0f);
    float dx = d.x*0.1f, dy = d.y*0.1f, dw = d.z*0.2f, dh = d.w*0.2f;
    float pcx = dx*w + cx;
    float pcy = dy*h + cy;
    float pw  = expf(dw)*w;
    float ph  = expf(dh)*h;
    bx1 = fminf(fmaxf(pcx - 0.5f*(pw - 1.0f), 0.0f), W);
    by1 = fminf(fmaxf(pcy - 0.5f*(ph - 1.0f), 0.0f), H);
    bx2 = fminf(fmaxf(pcx + 0.5f*(pw - 1.0f), 0.0f), W);
    by2 = fminf(fmaxf(pcy + 0.5f*(ph - 1.0f), 0.0f), H);
}

// ---------------- K1: 4 rois per thread, vectorized ----------------
__global__ void k1_score(const float* __restrict__ cls,
                         const float* __restrict__ bbox,
                         const float* __restrict__ rois,
                         const float* __restrict__ iminfo,
                         int ngrp, int n)
{
    int g = blockIdx.x*blockDim.x + threadIdx.x;
    if (g >= ngrp) return;
    int base = g * 4;
    bool full = (base + 4 <= n);

    float c[20], r[20];
    if (full) {
        const float4* c4 = reinterpret_cast<const float4*>(cls)  + (size_t)g*5;
        const float4* r4 = reinterpret_cast<const float4*>(rois) + (size_t)g*5;
        #pragma unroll
        for (int q = 0; q < 5; q++) {
            float4 t = c4[q];
            c[4*q]=t.x; c[4*q+1]=t.y; c[4*q+2]=t.z; c[4*q+3]=t.w;
        }
        #pragma unroll
        for (int q = 0; q < 5; q++) {
            float4 t = r4[q];
            r[4*q]=t.x; r[4*q+1]=t.y; r[4*q+2]=t.z; r[4*q+3]=t.w;
        }
    } else {
        #pragma unroll
        for (int q = 0; q < 4; q++) {
            if (base + q < n) {
                #pragma unroll
                for (int e = 0; e < 5; e++) {
                    c[q*5+e] = cls [(size_t)(base+q)*5 + e];
                    r[q*5+e] = rois[(size_t)(base+q)*5 + e];
                }
            }
        }
    }

    float W = iminfo[1] - 1.0f, H = iminfo[0] - 1.0f;
    unsigned short outb[4];

    #pragma unroll
    for (int q = 0; q < 4; q++) {
        unsigned short b = 0xFFFFu;
        if (base + q < n) {
            float s0=c[q*5], s1=c[q*5+1], s2=c[q*5+2], s3=c[q*5+3], s4=c[q*5+4];
            float m = s1; int a = 1;
            if (s2 > m) { m = s2; a = 2; }
            if (s3 > m) { m = s3; a = 3; }
            if (s4 > m) { m = s4; a = 4; }
            if ((1.0f - s0 >= 0.2f) && (m > 0.1f)) {
                float4 d = *reinterpret_cast<const float4*>(
                    bbox + (size_t)(base+q)*20 + a*4);
                float bx1, by1, bx2, by2;
                decode_core(r[q*5+1], r[q*5+2], r[q*5+3], r[q*5+4],
                            d, W, H, bx1, by1, bx2, by2);
                float bw = bx2 - bx1 + 1.0f;
                float bh = by2 - by1 + 1.0f;
                if (bw >= 6.0f || bh >= 6.0f) {
                    int bin = (int)(m * 65536.0f);
                    bin = min(max(bin, 0), NBINS - 2);   // 65535 reserved: invalid
                    b = (unsigned short)bin;
                    atomicAdd(&g_hist[bin], 1u);
                }
            }
        }
        outb[q] = b;
    }

    if (full) {
        *reinterpret_cast<ushort4*>(g_bins + base) =
            make_ushort4(outb[0], outb[1], outb[2], outb[3]);
    } else {
        #pragma unroll
        for (int q = 0; q < 4; q++)
            if (base + q < n) g_bins[base + q] = outb[q];
    }
}

// ------- K2: find threshold bin for top-300 (suffix scan), then zero hist ----
__global__ void k2_thresh() {
    __shared__ unsigned int part[1024];
    __shared__ int thr_sh;
    int t = threadIdx.x;
    if (t == 0) thr_sh = 0;

    unsigned int s = 0;
    int cbase = t * (NBINS/1024);            // 64 bins per thread
    #pragma unroll 8
    for (int b = 0; b < NBINS/1024; b++) s += g_hist[cbase + b];
    part[t] = s;
    __syncthreads();

    #pragma unroll
    for (int d = 1; d < 1024; d <<= 1) {
        unsigned int v = part[t] + ((t + d < 1024) ? part[t + d] : 0u);
        __syncthreads();
        part[t] = v;
        __syncthreads();
    }

    bool owner = (part[t] >= (unsigned)MAXC) &&
                 (t == 1023 || part[t + 1] < (unsigned)MAXC);
    if (owner) {
        unsigned int cum = (t == 1023) ? 0u : part[t + 1];
        for (int b = cbase + (NBINS/1024) - 1; b >= cbase; --b) {
            cum += g_hist[b];
            if (cum >= (unsigned)MAXC) { thr_sh = b; break; }
        }
    }
    __syncthreads();

    // zero histogram for next replay (16B stores)
    uint4* h4 = reinterpret_cast<uint4*>(g_hist);
    #pragma unroll
    for (int j = 0; j < 16; j++) h4[t*16 + j] = make_uint4(0,0,0,0);

    if (t == 0) g_thrbin = thr_sh;
}

// ---------------- K3: collect candidates above threshold ----------------
__global__ void k3_collect(const float* __restrict__ cls, int ngrp8, int n) {
    int g = blockIdx.x*blockDim.x + threadIdx.x;
    if (g >= ngrp8) return;
    uint4 v = reinterpret_cast<const uint4*>(g_bins)[g];
    unsigned int w[4] = {v.x, v.y, v.z, v.w};
    int thr = g_thrbin;
    int base = g * 8;
    #pragma unroll
    for (int l = 0; l < 8; l++) {
        unsigned int b = (w[l >> 1] >> ((l & 1) * 16)) & 0xFFFFu;
        int i = base + l;
        if (b != 0xFFFFu && (int)b >= thr && i < n) {
            const float* c = cls + (size_t)i*5;
            float m = fmaxf(fmaxf(c[1], c[2]), fmaxf(c[3], c[4]));
            unsigned int pos = atomicAdd(&g_count, 1u);
            if (pos < CAP) {
                g_cand[pos] =
                    (((unsigned long long)(~__float_as_uint(m))) << 32) |
                    (unsigned int)i;
            }
        }
    }
}

// --------- K4: rank-sort + decode + bitmatrix NMS + output + reset ----------
#define K4T 512

__global__ void k4_final(const float* __restrict__ cls,
                         const float* __restrict__ bbox,
                         const float* __restrict__ rois,
                         const float* __restrict__ iminfo,
                         float* __restrict__ out)
{
    __shared__ unsigned long long keys[CAP];   // raw keys; later reused as rm[]
    __shared__ unsigned long long skey[MAXC];  // top-300 sorted
    __shared__ float bx[MAXC][4];
    __shared__ float pr[MAXC][5];
    __shared__ float area[MAXC];
    __shared__ int   kept[TOPN];
    __shared__ int   nkept;

    int tid = threadIdx.x;
    int M = (int)min(g_count, (unsigned int)CAP);
    int K = min(M, MAXC);

    for (int t = tid; t < M; t += K4T) keys[t] = g_cand[t];
    __syncthreads();

    // rank-sort: keys are unique (idx in low 32 bits); ascending key order
    // == (score desc, idx asc). Scatter ranks < MAXC straight into skey.
    for (int t = tid; t < M; t += K4T) {
        unsigned long long k = keys[t];
        int r = 0;
        for (int j = 0; j < M; j++) r += (keys[j] < k);
        if (r < MAXC) skey[r] = k;
    }
    __syncthreads();

    float W = iminfo[1] - 1.0f, H = iminfo[0] - 1.0f;

    // decode top-K candidates
    for (int t = tid; t < K; t += K4T) {
        int i = (int)(unsigned int)(skey[t] & 0xFFFFFFFFULL);
        const float* c = cls + (size_t)i*5;
        float c0=c[0], c1=c[1], c2=c[2], c3=c[3], c4=c[4];
        pr[t][0]=c0; pr[t][1]=c1; pr[t][2]=c2; pr[t][3]=c3; pr[t][4]=c4;
        float m = c1; int a = 1;
        if (c2 > m) { m = c2; a = 2; }
        if (c3 > m) { m = c3; a = 3; }
        if (c4 > m) { m = c4; a = 4; }
        float4 d = *reinterpret_cast<const float4*>(bbox + (size_t)i*20 + a*4);
        float bx1, by1, bx2, by2;
        decode_core(rois[(size_t)i*5+1], rois[(size_t)i*5+2],
                    rois[(size_t)i*5+3], rois[(size_t)i*5+4],
                    d, W, H, bx1, by1, bx2, by2);
        bx[t][0]=bx1; bx[t][1]=by1; bx[t][2]=bx2; bx[t][3]=by2;
        area[t] = (bx2 - bx1) * (by2 - by1);
    }
    __syncthreads();

    // suppression bitmatrix (reuse keys storage): rm[i*5+w] bit b => iou>0.5, j>i
    unsigned long long* rm = keys;
    const int NW = (MAXC + 63) / 64;  // 5
    for (int task = tid; task < K * NW; task += K4T) {
        int i = task / NW;
        int w = task % NW;
        float ax1=bx[i][0], ay1=bx[i][1], ax2=bx[i][2], ay2=bx[i][3], aa=area[i];
        unsigned long long bits = 0ULL;
        int j0 = w * 64;
        int jend = min(j0 + 64, K);
        for (int j = max(j0, i+1); j < jend; j++) {
            float lx = fmaxf(ax1, bx[j][0]);
            float ly = fmaxf(ay1, bx[j][1]);
            float rx = fminf(ax2, bx[j][2]);
            float ry = fminf(ay2, bx[j][3]);
            float iw = fmaxf(rx - lx, 0.0f);
            float ih = fmaxf(ry - ly, 0.0f);
            float inter = iw * ih;
            float iou = inter / (aa + area[j] - inter);
            if (iou > 0.5f) bits |= 1ULL << (j - j0);
        }
        rm[i*NW + w] = bits;
    }
    __syncthreads();

    // greedy walk, fully register-resident (no dynamic register indexing)
    if (tid == 0) {
        unsigned long long sup1=0, sup2=0, sup3=0, sup4=0;
        int cnt = 0;

        #define WALK_WORD(WD, SUPIN, ORS)                                     \
        if (cnt < TOPN && K > (WD)*64) {                                      \
            int nb = K - (WD)*64; if (nb > 64) nb = 64;                       \
            unsigned long long alive =                                        \
                ((nb >= 64) ? ~0ULL : ((1ULL << nb) - 1ULL)) & ~(SUPIN);      \
            while (alive && cnt < TOPN) {                                     \
                int b = __ffsll((long long)alive) - 1;                        \
                int i = (WD)*64 + b;                                          \
                kept[cnt++] = i;                                              \
                alive &= ~rm[i*NW + (WD)];                                    \
                alive &= ~(1ULL << b);                                        \
                ORS                                                           \
            }                                                                 \
        }

        WALK_WORD(0, 0ULL,
            { sup1 |= rm[i*NW+1]; sup2 |= rm[i*NW+2];
              sup3 |= rm[i*NW+3]; sup4 |= rm[i*NW+4]; })
        WALK_WORD(1, sup1,
            { sup2 |= rm[i*NW+2]; sup3 |= rm[i*NW+3]; sup4 |= rm[i*NW+4]; })
        WALK_WORD(2, sup2,
            { sup3 |= rm[i*NW+3]; sup4 |= rm[i*NW+4]; })
        WALK_WORD(3, sup3,
            { sup4 |= rm[i*NW+4]; })
        WALK_WORD(4, sup4, { })
        #undef WALK_WORD

        nkept = cnt;
    }
    __syncthreads();

    for (int t = tid; t < TOPN*10; t += K4T) out[t] = 0.0f;
    __syncthreads();
    int nk = nkept;
    for (int r = tid; r < nk; r += K4T) {
        int i = kept[r];
        float* o = out + r*10;
        o[0] = 0.0f;
        o[1] = bx[i][0]; o[2] = bx[i][1]; o[3] = bx[i][2]; o[4] = bx[i][3];
        o[5] = pr[i][0]; o[6] = pr[i][1]; o[7] = pr[i][2]; o[8] = pr[i][3]; o[9] = pr[i][4];
    }

    if (tid == 0) g_count = 0u;   // reset for next graph replay
}

// ---------------- launch ----------------
extern "C" void kernel_launch(void* const* d_in, const int* in_sizes, int n_in,
                              void* d_out, int out_size)
{
    const float* cls    = (const float*)d_in[0];
    const float* bbox   = (const float*)d_in[1];
    const float* rois   = (const float*)d_in[2];
    const float* iminfo = (const float*)d_in[3];
    float* out = (float*)d_out;
    int n = in_sizes[0] / 5;
    if (n > MAXN) n = MAXN;

    int ngrp4 = (n + 3) / 4;
    int ngrp8 = (n + 7) / 8;

    k1_score <<<(ngrp4 + 255)/256, 256>>>(cls, bbox, rois, iminfo, ngrp4, n);
    k2_thresh<<<1, 1024>>>();
    k3_collect<<<(ngrp8 + 255)/256, 256>>>(cls, ngrp8, n);
    k4_final <<<1, K4T>>>(cls, bbox, rois, iminfo, out);
}